// round 4
// baseline (speedup 1.0000x reference)
#include <cuda_runtime.h>
#include <cstdint>

#define TT 4096   // tokens = B*S
#define HH 1024   // hidden
#define FF 4096   // ffn
#define NE 8      // experts

#define BM 128
#define BN 128
#define BK 32
#define STAGES 3
#define NT1 (FF / BN)               // 32 n-tiles for fc1
#define NT2 (HH / BN)               // 8 n-tiles for fc2
#define STAGE_BYTES 32768           // A 16KB + B 16KB
#define SMEM_BYTES (STAGES * STAGE_BYTES + 256)
#define GRID_GEMM 296               // 148 SMs x 2 CTAs

// ---------------- scratch (static device globals; no runtime alloc) --------
__device__ float g_mid[(size_t)(TT + BM) * FF];   // fc1 out (perm order, tf32-rounded)
__device__ int   g_perm[TT];
__device__ int   g_expert_of[TT];
__device__ float g_maxprob[TT];
__device__ int   g_cnt[NE];
__device__ int   g_off[NE + 1];
__device__ int   g_cur[NE];
__device__ int   g_work1[1536];     // packed (e<<20)|(nt<<8)|mt
__device__ int   g_work2[512];
__device__ int   g_nw1, g_nw2;
__device__ int   g_tick1, g_tick2;

// ---------------- helpers ---------------------------------------------------
__device__ __forceinline__ uint32_t smem_u32(const void* p) {
    uint32_t a;
    asm("{ .reg .u64 t; cvta.to.shared.u64 t, %1; cvt.u32.u64 %0, t; }" : "=r"(a) : "l"(p));
    return a;
}
__device__ __forceinline__ float to_tf32(float x) {
    uint32_t u;
    asm("cvt.rna.tf32.f32 %0, %1;" : "=r"(u) : "f"(x));
    return __uint_as_float(u);
}
__device__ __forceinline__ uint32_t to_tf32_u(float x) {
    uint32_t u;
    asm("cvt.rna.tf32.f32 %0, %1;" : "=r"(u) : "f"(x));
    return u;
}
__device__ __forceinline__ float gelu_exact(float v) {
    return 0.5f * v * (1.0f + erff(v * 0.7071067811865476f));
}
__device__ __forceinline__ void cp_async16(uint32_t dst, const void* src) {
    asm volatile("cp.async.cg.shared.global [%0], [%1], 16;" :: "r"(dst), "l"(src));
}
__device__ __forceinline__ void cp_commit() {
    asm volatile("cp.async.commit_group;" ::: "memory");
}
template<int N>
__device__ __forceinline__ void cp_wait() {
    asm volatile("cp.async.wait_group %0;" :: "n"(N) : "memory");
}

// ---------------- routing / planning kernels --------------------------------
__global__ void init_kernel() {
    if (threadIdx.x < NE) g_cnt[threadIdx.x] = 0;
}

__global__ void router_kernel(const float* __restrict__ x,
                              const float* __restrict__ Wr,
                              const float* __restrict__ br) {
    int warp = (blockIdx.x * blockDim.x + threadIdx.x) >> 5;
    int lane = threadIdx.x & 31;
    if (warp >= TT) return;
    const float* xr = x + (size_t)warp * HH;
    float acc[NE];
#pragma unroll
    for (int e = 0; e < NE; e++) acc[e] = 0.f;
    for (int i = lane; i < HH; i += 32) {
        float xv = xr[i];
        const float4* w4 = reinterpret_cast<const float4*>(Wr + i * NE);
        float4 w0 = w4[0], w1 = w4[1];
        acc[0] += xv * w0.x; acc[1] += xv * w0.y;
        acc[2] += xv * w0.z; acc[3] += xv * w0.w;
        acc[4] += xv * w1.x; acc[5] += xv * w1.y;
        acc[6] += xv * w1.z; acc[7] += xv * w1.w;
    }
#pragma unroll
    for (int e = 0; e < NE; e++) {
#pragma unroll
        for (int o = 16; o > 0; o >>= 1)
            acc[e] += __shfl_xor_sync(0xffffffffu, acc[e], o);
    }
    if (lane == 0) {
        float best = acc[0] + br[0]; int bi = 0;
#pragma unroll
        for (int e = 1; e < NE; e++) {
            float v = acc[e] + br[e];
            if (v > best) { best = v; bi = e; }
        }
        g_expert_of[warp] = bi;
        g_maxprob[warp]   = 1.0f / (1.0f + expf(-best));
        atomicAdd(&g_cnt[bi], 1);
    }
}

// offsets + work lists + ticket reset (single thread; trivial volume)
__global__ void scanplan_kernel() {
    if (threadIdx.x != 0) return;
    int off = 0;
    int nm[NE];
    for (int e = 0; e < NE; e++) {
        g_off[e] = off; g_cur[e] = off;
        nm[e] = (g_cnt[e] + BM - 1) / BM;
        off += g_cnt[e];
    }
    g_off[NE] = off;
    int n1 = 0;
    for (int e = 0; e < NE; e++)
        for (int nt = 0; nt < NT1; nt++)
            for (int mt = 0; mt < nm[e]; mt++)
                g_work1[n1++] = (e << 20) | (nt << 8) | mt;
    int n2 = 0;
    for (int e = 0; e < NE; e++)
        for (int nt = 0; nt < NT2; nt++)
            for (int mt = 0; mt < nm[e]; mt++)
                g_work2[n2++] = (e << 20) | (nt << 8) | mt;
    g_nw1 = n1; g_nw2 = n2;
    g_tick1 = 0; g_tick2 = 0;
}

__global__ void perm_kernel() {
    int t = blockIdx.x * blockDim.x + threadIdx.x;
    if (t < TT) {
        int e = g_expert_of[t];
        int slot = atomicAdd(&g_cur[e], 1);
        g_perm[slot] = t;
    }
}

// ---------------- persistent pipelined tf32 grouped GEMM --------------------
// FC1: g_mid = tf32( gelu( x[perm] @ W1[e] ) )   K=HH, N over FF (A rounded at use)
// FC2: out   = ( g_mid @ W2[e] ) * p             K=FF, N over HH (A pre-rounded)
//
// 256 threads, 8 warps (4 m x 2 n), warp tile 32x64, mma m16n8k8 tf32.
// Smem: A[128][32] 128B rows, chunk^(m&7) swizzle.
//       B[32][128] 512B rows, chunk^((k&3)<<1) swizzle.
template<int KTOT, bool FC2>
__global__ __launch_bounds__(256, 2)
void moe_gemm(const float* __restrict__ x,
              const float* __restrict__ W, float* __restrict__ outp) {
    constexpr int LDB = FC2 ? HH : FF;
    constexpr int KIT = KTOT / BK;

    extern __shared__ char smem_raw[];
    uint32_t s_u32 = smem_u32(smem_raw);
    uint32_t s0    = (s_u32 + 127u) & ~127u;
    char*    s_gen = smem_raw + (s0 - s_u32);
    int* s_w = reinterpret_cast<int*>(s_gen + STAGES * STAGE_BYTES);

    int tid = threadIdx.x, lane = tid & 31, wid = tid >> 5;
    int g = lane >> 2, t = lane & 3;
    int wm = wid >> 1, wn = wid & 1;
    int r0  = wm * 32;
    int nb0 = wn * 64;

    int am = tid >> 1;                 // A loader row
    int aj = (tid & 1) * 4;            // A loader chunk base
    int kr = tid >> 3;                 // B loader k-row
    int bj = tid & 7;                  // B loader chunk base
    uint32_t a_dst_rel = (uint32_t)am * 128u;
    uint32_t b_dst_rel = 16384u + (uint32_t)kr * 512u;
    uint32_t b_sw = (uint32_t)((kr & 3) << 1);

    const int nw = FC2 ? g_nw2 : g_nw1;
    int* tick    = FC2 ? &g_tick2 : &g_tick1;
    const int* worklist = FC2 ? g_work2 : g_work1;

    for (;;) {
        if (tid == 0) *s_w = atomicAdd(tick, 1);
        __syncthreads();               // broadcast + protects smem stage reuse
        int w = *s_w;
        if (w >= nw) return;
        int item = worklist[w];
        int e  = item >> 20;
        int nt = (item >> 8) & 0xfff;
        int mt = item & 0xff;

        int off0 = g_off[e];
        int cnt  = g_off[e + 1] - off0;
        int base = off0 + mt * BM;
        int n0   = nt * BN;
        const float* Be = W + (size_t)e * KTOT * LDB;

        // A row pointer for this tile
        const float* Arow;
        if (FC2) {
            Arow = g_mid + (size_t)(base + am) * KTOT;
        } else {
            int idx = base + am;
            int lim = off0 + cnt - 1;
            int tok = g_perm[idx < lim ? idx : lim];
            Arow = x + (size_t)tok * HH;
        }
        const float* Brow0 = Be + (size_t)kr * LDB + n0;

        float acc[2][8][4];
#pragma unroll
        for (int mi = 0; mi < 2; mi++)
#pragma unroll
            for (int ni = 0; ni < 8; ni++)
#pragma unroll
                for (int c = 0; c < 4; c++) acc[mi][ni][c] = 0.f;

        auto issue_load = [&](int it) {
            uint32_t sb = (uint32_t)((it % STAGES) * STAGE_BYTES);
            int kb = it * BK;
            const float* as = Arow + kb + aj * 4;
#pragma unroll
            for (int c = 0; c < 4; c++) {
                uint32_t ch = (uint32_t)(aj + c);
                cp_async16(s0 + a_dst_rel + sb + ((ch ^ (uint32_t)(am & 7)) << 4),
                           as + c * 4);
            }
            const float* bs = Brow0 + (size_t)kb * LDB;
#pragma unroll
            for (int c = 0; c < 4; c++) {
                uint32_t ch = (uint32_t)(bj + 8 * c);
                cp_async16(s0 + b_dst_rel + sb + ((ch ^ b_sw) << 4), bs + ch * 4);
            }
        };

#pragma unroll
        for (int s = 0; s < STAGES - 1; s++) {
            issue_load(s);
            cp_commit();
        }

        for (int it = 0; it < KIT; it++) {
            cp_wait<STAGES - 2>();
            __syncthreads();
            int nx = it + STAGES - 1;
            if (nx < KIT) issue_load(nx);
            cp_commit();

            char* sA = s_gen + (it % STAGES) * STAGE_BYTES;
            char* sB = sA + 16384;

#pragma unroll
            for (int ks = 0; ks < 4; ks++) {
                // ---- A fragments ----
                uint32_t a[2][4];
#pragma unroll
                for (int mi = 0; mi < 2; mi++) {
                    int r = r0 + mi * 16 + g;
                    char* rowp  = sA + r * 128;
                    char* rowp8 = sA + (r + 8) * 128;
                    uint32_t c0 = (uint32_t)((2 * ks) ^ g) << 4;
                    uint32_t c1 = (uint32_t)((2 * ks + 1) ^ g) << 4;
                    if (FC2) {   // pre-rounded in gmem
                        a[mi][0] = *(const uint32_t*)(rowp  + c0 + t * 4);
                        a[mi][1] = *(const uint32_t*)(rowp8 + c0 + t * 4);
                        a[mi][2] = *(const uint32_t*)(rowp  + c1 + t * 4);
                        a[mi][3] = *(const uint32_t*)(rowp8 + c1 + t * 4);
                    } else {     // round RNE here
                        a[mi][0] = to_tf32_u(*(const float*)(rowp  + c0 + t * 4));
                        a[mi][1] = to_tf32_u(*(const float*)(rowp8 + c0 + t * 4));
                        a[mi][2] = to_tf32_u(*(const float*)(rowp  + c1 + t * 4));
                        a[mi][3] = to_tf32_u(*(const float*)(rowp8 + c1 + t * 4));
                    }
                }
                // ---- B fragments (round RNE here) ----
                uint32_t b[8][2];
                char* bk0 = sB + (ks * 8 + t) * 512;
#pragma unroll
                for (int ni = 0; ni < 8; ni++) {
                    uint32_t chn = (uint32_t)((nb0 >> 2) + 2 * ni + (g >> 2));
                    uint32_t off = ((chn ^ (uint32_t)(t << 1)) << 4) + (uint32_t)(g & 3) * 4;
                    b[ni][0] = to_tf32_u(*(const float*)(bk0 + off));
                    b[ni][1] = to_tf32_u(*(const float*)(bk0 + 2048 + off));
                }
#pragma unroll
                for (int mi = 0; mi < 2; mi++)
#pragma unroll
                    for (int ni = 0; ni < 8; ni++) {
                        asm volatile(
                            "mma.sync.aligned.m16n8k8.row.col.f32.tf32.tf32.f32 "
                            "{%0,%1,%2,%3}, {%4,%5,%6,%7}, {%8,%9}, {%0,%1,%2,%3};\n"
                            : "+f"(acc[mi][ni][0]), "+f"(acc[mi][ni][1]),
                              "+f"(acc[mi][ni][2]), "+f"(acc[mi][ni][3])
                            : "r"(a[mi][0]), "r"(a[mi][1]), "r"(a[mi][2]), "r"(a[mi][3]),
                              "r"(b[ni][0]), "r"(b[ni][1]));
                    }
            }
        }

        // ---------------- epilogue ----------------
#pragma unroll
        for (int mi = 0; mi < 2; mi++) {
#pragma unroll
            for (int half = 0; half < 2; half++) {
                int row = r0 + mi * 16 + half * 8 + g;
                if (mt * BM + row >= cnt) continue;
                if (!FC2) {
                    float* op = g_mid + (size_t)(base + row) * FF + n0;
#pragma unroll
                    for (int ni = 0; ni < 8; ni++) {
                        float2 v;
                        v.x = to_tf32(gelu_exact(acc[mi][ni][half * 2 + 0]));
                        v.y = to_tf32(gelu_exact(acc[mi][ni][half * 2 + 1]));
                        *reinterpret_cast<float2*>(op + nb0 + ni * 8 + 2 * t) = v;
                    }
                } else {
                    int token = g_perm[base + row];
                    float p = g_maxprob[token];
                    float* op = outp + (size_t)token * HH + n0;
#pragma unroll
                    for (int ni = 0; ni < 8; ni++) {
                        float2 v;
                        v.x = acc[mi][ni][half * 2 + 0] * p;
                        v.y = acc[mi][ni][half * 2 + 1] * p;
                        *reinterpret_cast<float2*>(op + nb0 + ni * 8 + 2 * t) = v;
                    }
                }
            }
        }
    }
}

// ---------------- launch ----------------------------------------------------
extern "C" void kernel_launch(void* const* d_in, const int* in_sizes, int n_in,
                              void* d_out, int out_size) {
    const float* x  = (const float*)d_in[0];
    const float* Wr = (const float*)d_in[1];
    const float* br = (const float*)d_in[2];
    const float* W1 = (const float*)d_in[3];
    const float* W2 = (const float*)d_in[4];
    float* out = (float*)d_out;

    cudaFuncSetAttribute(moe_gemm<HH, false>,
                         cudaFuncAttributeMaxDynamicSharedMemorySize, SMEM_BYTES);
    cudaFuncSetAttribute(moe_gemm<FF, true>,
                         cudaFuncAttributeMaxDynamicSharedMemorySize, SMEM_BYTES);

    init_kernel<<<1, 32>>>();
    router_kernel<<<TT / 4, 128>>>(x, Wr, br);
    scanplan_kernel<<<1, 32>>>();
    perm_kernel<<<TT / 256, 256>>>();
    moe_gemm<HH, false><<<GRID_GEMM, 256, SMEM_BYTES>>>(x, W1, nullptr);
    moe_gemm<FF, true ><<<GRID_GEMM, 256, SMEM_BYTES>>>(x, W2, out);
}

// round 5
// speedup vs baseline: 1.6983x; 1.6983x over previous
#include <cuda_runtime.h>
#include <cuda_fp16.h>
#include <cstdint>

#define TT 4096   // tokens = B*S
#define HH 1024   // hidden
#define FF 4096   // ffn
#define NE 8      // experts

#define BM 128
#define BN 128
#define BK 32
#define STAGES 4
#define TILES_M (TT / BM)           // 32 per expert (worst case)
#define STAGE_BYTES 24576           // A(fp16) 8KB + B(fp32) 16KB
#define SMEM_BYTES (STAGES * STAGE_BYTES + 256)

// ---------------- scratch (static device globals; no runtime alloc) --------
__device__ __half g_xg [(size_t)(TT + BM) * HH];  // gathered acts, fp16
__device__ __half g_mid[(size_t)(TT + BM) * FF];  // fc1 out (perm order), fp16
__device__ int    g_perm[TT];
__device__ int    g_expert_of[TT];
__device__ float  g_maxprob[TT];
__device__ int    g_cnt[NE];
__device__ int    g_off[NE + 1];
__device__ int    g_cur[NE];

// ---------------- helpers ---------------------------------------------------
__device__ __forceinline__ uint32_t smem_u32(const void* p) {
    uint32_t a;
    asm("{ .reg .u64 t; cvta.to.shared.u64 t, %1; cvt.u32.u64 %0, t; }" : "=r"(a) : "l"(p));
    return a;
}
// pack two f32 -> f16x2 (first src -> HIGH half, second -> LOW half)
__device__ __forceinline__ uint32_t pack_f16x2(float hi, float lo) {
    uint32_t d;
    asm("cvt.rn.f16x2.f32 %0, %1, %2;" : "=r"(d) : "f"(hi), "f"(lo));
    return d;
}
__device__ __forceinline__ float gelu_exact(float v) {
    return 0.5f * v * (1.0f + erff(v * 0.7071067811865476f));
}
__device__ __forceinline__ void cp_async16(uint32_t dst, const void* src) {
    asm volatile("cp.async.cg.shared.global [%0], [%1], 16;" :: "r"(dst), "l"(src));
}
__device__ __forceinline__ void cp_commit() {
    asm volatile("cp.async.commit_group;" ::: "memory");
}
template<int N>
__device__ __forceinline__ void cp_wait() {
    asm volatile("cp.async.wait_group %0;" :: "n"(N) : "memory");
}

// ---------------- routing kernels ------------------------------------------
__global__ void init_kernel() {
    if (threadIdx.x < NE) g_cnt[threadIdx.x] = 0;
}

__global__ void router_kernel(const float* __restrict__ x,
                              const float* __restrict__ Wr,
                              const float* __restrict__ br) {
    int warp = (blockIdx.x * blockDim.x + threadIdx.x) >> 5;
    int lane = threadIdx.x & 31;
    if (warp >= TT) return;
    const float* xr = x + (size_t)warp * HH;
    float acc[NE];
#pragma unroll
    for (int e = 0; e < NE; e++) acc[e] = 0.f;
    for (int i = lane; i < HH; i += 32) {
        float xv = xr[i];
        const float4* w4 = reinterpret_cast<const float4*>(Wr + i * NE);
        float4 w0 = w4[0], w1 = w4[1];
        acc[0] += xv * w0.x; acc[1] += xv * w0.y;
        acc[2] += xv * w0.z; acc[3] += xv * w0.w;
        acc[4] += xv * w1.x; acc[5] += xv * w1.y;
        acc[6] += xv * w1.z; acc[7] += xv * w1.w;
    }
#pragma unroll
    for (int e = 0; e < NE; e++) {
#pragma unroll
        for (int o = 16; o > 0; o >>= 1)
            acc[e] += __shfl_xor_sync(0xffffffffu, acc[e], o);
    }
    if (lane == 0) {
        float best = acc[0] + br[0]; int bi = 0;
#pragma unroll
        for (int e = 1; e < NE; e++) {
            float v = acc[e] + br[e];
            if (v > best) { best = v; bi = e; }
        }
        g_expert_of[warp] = bi;
        g_maxprob[warp]   = 1.0f / (1.0f + expf(-best));
        atomicAdd(&g_cnt[bi], 1);
    }
}

__global__ void scan_kernel() {
    if (threadIdx.x == 0) {
        int off = 0;
        for (int e = 0; e < NE; e++) {
            g_off[e] = off; g_cur[e] = off; off += g_cnt[e];
        }
        g_off[NE] = off;
    }
}

__global__ void perm_kernel() {
    int t = blockIdx.x * blockDim.x + threadIdx.x;
    if (t < TT) {
        int e = g_expert_of[t];
        int slot = atomicAdd(&g_cur[e], 1);
        g_perm[slot] = t;
    }
}

// gather x rows into perm order as fp16 (one block per slot)
__global__ void gather_kernel(const float* __restrict__ x) {
    int slot = blockIdx.x;
    int tok  = g_perm[slot];
    const float4* src = reinterpret_cast<const float4*>(x + (size_t)tok * HH);
    int c = threadIdx.x;            // 256 threads, 4 elems each
    float4 v = src[c];
    __half2 h0 = __floats2half2_rn(v.x, v.y);   // x -> low
    __half2 h1 = __floats2half2_rn(v.z, v.w);
    uint2 pk;
    pk.x = *reinterpret_cast<uint32_t*>(&h0);
    pk.y = *reinterpret_cast<uint32_t*>(&h1);
    *reinterpret_cast<uint2*>(g_xg + (size_t)slot * HH + 4 * c) = pk;
}

// ---------------- pipelined fp16 grouped GEMM ------------------------------
// FC1: g_mid = fp16( gelu( g_xg @ W1[e] ) )   K=HH, N over FF
// FC2: out   = ( g_mid @ W2[e] ) * p          K=FF, N over HH
//
// 256 threads, 8 warps (4 m x 2 n), warp tile 32x64, mma m16n8k16 f16.f16.f32.
// Smem A': fp16 [128][32], 64B rows, chunk16 ^ ((m>>1)&3) swizzle.
// Smem B : fp32 [32][128], 512B rows, chunk16 ^ (k&7) swizzle.
template<int KTOT, bool FC2>
__global__ __launch_bounds__(256, 2)
void moe_gemm(const float* __restrict__ W, float* __restrict__ outp) {
    constexpr int LDB = FC2 ? HH : FF;
    constexpr int KIT = KTOT / BK;

    int e  = blockIdx.x >> 5;
    int mt = blockIdx.x & 31;
    int off0 = g_off[e];
    int cnt  = g_off[e + 1] - off0;
    if (mt * BM >= cnt) return;
    int base = off0 + mt * BM;
    int n0   = blockIdx.y * BN;
    const float* Be = W + (size_t)e * KTOT * LDB;
    const __half* Abase = (FC2 ? g_mid : g_xg) + (size_t)base * KTOT;

    extern __shared__ char smem_raw[];
    uint32_t s_u32 = smem_u32(smem_raw);
    uint32_t s0    = (s_u32 + 127u) & ~127u;
    char*    s_gen = smem_raw + (s0 - s_u32);

    int tid = threadIdx.x, lane = tid & 31, wid = tid >> 5;
    int g = lane >> 2, t = lane & 3;
    int wm = wid >> 1, wn = wid & 1;
    int r0  = wm * 32;
    int nb0 = wn * 64;

    // A loader: row am = tid>>1, chunks jc = (tid&1)*2 + {0,1} (16B = 8 halfs)
    int am = tid >> 1;
    int aj = (tid & 1) * 2;
    const __half* Arow = Abase + (size_t)am * KTOT;
    uint32_t a_dst_base = s0 + (uint32_t)am * 64u;
    uint32_t a_sw = (uint32_t)((am >> 1) & 3);
    // B loader: row kr = tid>>3, chunks bj + 8c (16B = 4 floats)
    int kr = tid >> 3;
    int bj = tid & 7;
    const float* Brow0 = Be + (size_t)kr * LDB + n0;
    uint32_t b_dst_base = s0 + 8192u + (uint32_t)kr * 512u;
    uint32_t b_sw = (uint32_t)(kr & 7);

    float acc[2][8][4];
#pragma unroll
    for (int mi = 0; mi < 2; mi++)
#pragma unroll
        for (int ni = 0; ni < 8; ni++)
#pragma unroll
            for (int c = 0; c < 4; c++) acc[mi][ni][c] = 0.f;

    auto issue_load = [&](int it) {
        uint32_t sb = (uint32_t)((it % STAGES) * STAGE_BYTES);
        int kb = it * BK;
        const __half* as = Arow + kb + aj * 8;
#pragma unroll
        for (int c = 0; c < 2; c++) {
            uint32_t ch = (uint32_t)(aj + c);
            cp_async16(a_dst_base + sb + ((ch ^ a_sw) << 4), as + c * 8);
        }
        const float* bs = Brow0 + (size_t)kb * LDB;
#pragma unroll
        for (int c = 0; c < 4; c++) {
            uint32_t ch = (uint32_t)(bj + 8 * c);
            cp_async16(b_dst_base + sb + ((ch ^ b_sw) << 4), bs + ch * 4);
        }
    };

#pragma unroll
    for (int s = 0; s < STAGES - 1; s++) {
        if (s < KIT) issue_load(s);
        cp_commit();
    }

    for (int it = 0; it < KIT; it++) {
        cp_wait<STAGES - 2>();
        __syncthreads();
        int nx = it + STAGES - 1;
        if (nx < KIT) issue_load(nx);
        cp_commit();

        char* sA = s_gen + (it % STAGES) * STAGE_BYTES;
        char* sB = sA + 8192;

#pragma unroll
        for (int ks = 0; ks < 2; ks++) {          // two k16 steps per BK=32
            // ---- A fragments: native half2 LDS.32 ----
            uint32_t a[2][4];
#pragma unroll
            for (int mi = 0; mi < 2; mi++) {
                int RA = r0 + mi * 16 + g;
                int RB = RA + 8;
                uint32_t c0 = (uint32_t)(ks * 2);
                uint32_t c1 = c0 + 1;
                uint32_t oA0 = (uint32_t)RA * 64u + (((c0 ^ (uint32_t)((RA >> 1) & 3))) << 4) + 4u * t;
                uint32_t oA1 = (uint32_t)RA * 64u + (((c1 ^ (uint32_t)((RA >> 1) & 3))) << 4) + 4u * t;
                uint32_t oB0 = (uint32_t)RB * 64u + (((c0 ^ (uint32_t)((RB >> 1) & 3))) << 4) + 4u * t;
                uint32_t oB1 = (uint32_t)RB * 64u + (((c1 ^ (uint32_t)((RB >> 1) & 3))) << 4) + 4u * t;
                a[mi][0] = *(const uint32_t*)(sA + oA0);
                a[mi][1] = *(const uint32_t*)(sA + oB0);
                a[mi][2] = *(const uint32_t*)(sA + oA1);
                a[mi][3] = *(const uint32_t*)(sA + oB1);
            }
            // ---- B fragments: fp32 LDS + RNE pack to f16x2 ----
            uint32_t b[8][2];
            int k0 = ks * 16;
            int ke = k0 + 2 * t;          // even k row for reg0
            int ko = ke + 1;
            int ke8 = ke + 8, ko8 = ko + 8;
#pragma unroll
            for (int ni = 0; ni < 8; ni++) {
                int n = nb0 + ni * 8 + g;
                uint32_t chunk = (uint32_t)(n >> 2);
                uint32_t w = (uint32_t)(n & 3) * 4u;
                float lo0 = *(const float*)(sB + ke  * 512 + ((chunk ^ (uint32_t)(ke  & 7)) << 4) + w);
                float hi0 = *(const float*)(sB + ko  * 512 + ((chunk ^ (uint32_t)(ko  & 7)) << 4) + w);
                float lo1 = *(const float*)(sB + ke8 * 512 + ((chunk ^ (uint32_t)(ke8 & 7)) << 4) + w);
                float hi1 = *(const float*)(sB + ko8 * 512 + ((chunk ^ (uint32_t)(ko8 & 7)) << 4) + w);
                b[ni][0] = pack_f16x2(hi0, lo0);
                b[ni][1] = pack_f16x2(hi1, lo1);
            }
#pragma unroll
            for (int mi = 0; mi < 2; mi++)
#pragma unroll
                for (int ni = 0; ni < 8; ni++) {
                    asm volatile(
                        "mma.sync.aligned.m16n8k16.row.col.f32.f16.f16.f32 "
                        "{%0,%1,%2,%3}, {%4,%5,%6,%7}, {%8,%9}, {%0,%1,%2,%3};\n"
                        : "+f"(acc[mi][ni][0]), "+f"(acc[mi][ni][1]),
                          "+f"(acc[mi][ni][2]), "+f"(acc[mi][ni][3])
                        : "r"(a[mi][0]), "r"(a[mi][1]), "r"(a[mi][2]), "r"(a[mi][3]),
                          "r"(b[ni][0]), "r"(b[ni][1]));
                }
        }
    }

    // ---------------- epilogue ----------------
#pragma unroll
    for (int mi = 0; mi < 2; mi++) {
#pragma unroll
        for (int half = 0; half < 2; half++) {
            int row = r0 + mi * 16 + half * 8 + g;
            if (mt * BM + row >= cnt) continue;
            if (!FC2) {
                __half* op = g_mid + (size_t)(base + row) * FF + n0;
#pragma unroll
                for (int ni = 0; ni < 8; ni++) {
                    __half2 hv = __floats2half2_rn(
                        gelu_exact(acc[mi][ni][half * 2 + 0]),
                        gelu_exact(acc[mi][ni][half * 2 + 1]));
                    *reinterpret_cast<__half2*>(op + nb0 + ni * 8 + 2 * t) = hv;
                }
            } else {
                int token = g_perm[base + row];
                float p = g_maxprob[token];
                float* op = outp + (size_t)token * HH + n0;
#pragma unroll
                for (int ni = 0; ni < 8; ni++) {
                    float2 v;
                    v.x = acc[mi][ni][half * 2 + 0] * p;
                    v.y = acc[mi][ni][half * 2 + 1] * p;
                    *reinterpret_cast<float2*>(op + nb0 + ni * 8 + 2 * t) = v;
                }
            }
        }
    }
}

// ---------------- launch ----------------------------------------------------
extern "C" void kernel_launch(void* const* d_in, const int* in_sizes, int n_in,
                              void* d_out, int out_size) {
    const float* x  = (const float*)d_in[0];
    const float* Wr = (const float*)d_in[1];
    const float* br = (const float*)d_in[2];
    const float* W1 = (const float*)d_in[3];
    const float* W2 = (const float*)d_in[4];
    float* out = (float*)d_out;

    cudaFuncSetAttribute(moe_gemm<HH, false>,
                         cudaFuncAttributeMaxDynamicSharedMemorySize, SMEM_BYTES);
    cudaFuncSetAttribute(moe_gemm<FF, true>,
                         cudaFuncAttributeMaxDynamicSharedMemorySize, SMEM_BYTES);

    init_kernel<<<1, 32>>>();
    router_kernel<<<TT / 4, 128>>>(x, Wr, br);
    scan_kernel<<<1, 32>>>();
    perm_kernel<<<TT / 256, 256>>>();
    gather_kernel<<<TT, 256>>>(x);
    moe_gemm<HH, false><<<dim3(TILES_M * NE, FF / BN), 256, SMEM_BYTES>>>(W1, nullptr);
    moe_gemm<FF, true ><<<dim3(TILES_M * NE, HH / BN), 256, SMEM_BYTES>>>(W2, out);
}